// round 6
// baseline (speedup 1.0000x reference)
#include <cuda_runtime.h>
#include <cstdint>

// B=64, N=1024, DIN=64, DH=128, H_MLP=128, L=3, C=4
// All GEMM operands pre-split to (tf32_hi, tf32_lo) uint2 pairs in gmem.
// Mainloop: LDS.64 + HMMA only. 3-term products: hh + lh + hl.
// Dynamic smem (67.5KB) to fit double-buffered split tiles.

#define BM 128
#define BN 128
#define BK 16
#define SW2 264                       // floats per smem row (128*2 + 8 pad)
#define TILE_F (BK * SW2)             // floats per tile stage
#define SMEM_BYTES (4 * TILE_F * 4)   // As[2] + Bs[2]

// split operand buffers (uint2 = hi,lo tf32 bit patterns)
__device__ uint2 eHa[1024 * 8192];
__device__ uint2 eHb[1024 * 8192];
__device__ uint2 eAGG[3u * 8388608u];
__device__ uint2 eM1[3u * 8388608u];
__device__ uint2 eM2[3u * 8388608u];
__device__ uint2 eU[3u * 1048576u];
__device__ uint2 eUcat[1024 * 3072];
__device__ uint2 eW1[3 * 128 * 128];
__device__ uint2 eW2[3 * 128 * 128];
__device__ float g_pooled[64 * 128];

__device__ __forceinline__ uint2* resolve(int tag) {
    switch (tag) {
        case 0: return eHa;  case 1: return eHb;  case 2: return eAGG;
        case 3: return eM1;  case 4: return eM2;  case 5: return eU;
        case 6: return eUcat; case 7: return eW1; default: return eW2;
    }
}

__device__ __forceinline__ uint2 splitf(float v) {
    uint32_t h;
    asm("cvt.rna.tf32.f32 %0, %1;" : "=r"(h) : "f"(v));
    float l = v - __uint_as_float(h);
    uint32_t lo;
    asm("cvt.rna.tf32.f32 %0, %1;" : "=r"(lo) : "f"(l));
    return make_uint2(h, lo);
}

#define MMA_TF32(d, a0, a1, a2, a3, b0, b1)                                  \
    asm volatile(                                                            \
        "mma.sync.aligned.m16n8k8.row.col.f32.tf32.tf32.f32 "                \
        "{%0,%1,%2,%3},{%4,%5,%6,%7},{%8,%9},{%0,%1,%2,%3};"                 \
        : "+f"(d[0]), "+f"(d[1]), "+f"(d[2]), "+f"(d[3])                     \
        : "r"(a0), "r"(a1), "r"(a2), "r"(a3), "r"(b0), "r"(b1))

// ---------------------------------------------------------------------------
__global__ void __launch_bounds__(256, 1)
gemm_ps(int tagA, long long aZ, int lda,
        int tagB, long long bZ, int ldb,
        int tagC, long long cZ, int ldc,
        int K,
        const float* __restrict__ bias, int biasZ,
        const float* __restrict__ bwPtr, int bwL,
        int transA, int reluFlag)
{
    extern __shared__ float smem[];
    float* AsBase = smem;                 // [2][BK][SW2]
    float* BsBase = smem + 2 * TILE_F;    // [2][BK][SW2]
#define AS(st, r, c) AsBase[(st) * TILE_F + (r) * SW2 + (c)]
#define BS(st, r, c) BsBase[(st) * TILE_F + (r) * SW2 + (c)]

    const int z = blockIdx.z;
    const uint2* A = resolve(tagA) + (long long)z * aZ;
    const uint2* B = resolve(tagB) + (long long)z * bZ;
    uint2*       C = resolve(tagC) + (long long)z * cZ;
    if (bias) bias += z * biasZ;

    const int bx = blockIdx.x, by = blockIdx.y;
    const int tid = threadIdx.x, warp = tid >> 5, lane = tid & 31;
    const int warpM = (warp >> 2) * 64, warpN = (warp & 3) * 32;
    const int lr = lane & 3, lc = lane >> 2;

    const int ldRow  = tid >> 5;            // 0..7
    const int ldCol2 = (tid & 31) * 2;      // elem index 0..62
    const int aRow   = tid >> 2;            // 0..63
    const int aq     = (tid & 3) * 2;       // k-elem offset 0,2,4,6

    float acc[4][4][4];
#pragma unroll
    for (int i = 0; i < 4; i++)
#pragma unroll
        for (int j = 0; j < 4; j++)
#pragma unroll
            for (int r = 0; r < 4; r++) acc[i][j][r] = 0.f;

    float4 rB[4], rA[4];
    auto load_gmem = [&](int k0) {
#pragma unroll
        for (int p = 0; p < 4; p++) {
            const int r = ldRow + (p & 1) * 8, c = ldCol2 + (p >> 1) * 64;
            rB[p] = *reinterpret_cast<const float4*>(B + (size_t)(k0 + r) * ldb + bx * BN + c);
        }
        if (transA) {
#pragma unroll
            for (int p = 0; p < 4; p++) {
                const int r = ldRow + (p & 1) * 8, c = ldCol2 + (p >> 1) * 64;
                rA[p] = *reinterpret_cast<const float4*>(A + (size_t)(k0 + r) * lda + by * BM + c);
            }
        } else {
#pragma unroll
            for (int p = 0; p < 4; p++) {
                const int m = aRow + (p & 1) * 64, kk = aq + (p >> 1) * 8;
                rA[p] = *reinterpret_cast<const float4*>(A + (size_t)(by * BM + m) * lda + k0 + kk);
            }
        }
    };
    auto store_smem = [&](int st) {
#pragma unroll
        for (int p = 0; p < 4; p++) {
            const int r = ldRow + (p & 1) * 8, c = ldCol2 + (p >> 1) * 64;
            *reinterpret_cast<float4*>(&BS(st, r, 2 * c)) = rB[p];
        }
        if (transA) {
#pragma unroll
            for (int p = 0; p < 4; p++) {
                const int r = ldRow + (p & 1) * 8, c = ldCol2 + (p >> 1) * 64;
                *reinterpret_cast<float4*>(&AS(st, r, 2 * c)) = rA[p];
            }
        } else {
#pragma unroll
            for (int p = 0; p < 4; p++) {
                const int m = aRow + (p & 1) * 64, kk = aq + (p >> 1) * 8;
                *reinterpret_cast<float2*>(&AS(st, kk, 2 * m))     = make_float2(rA[p].x, rA[p].y);
                *reinterpret_cast<float2*>(&AS(st, kk + 1, 2 * m)) = make_float2(rA[p].z, rA[p].w);
            }
        }
    };

    load_gmem(0);
    store_smem(0);
    __syncthreads();

    int cur = 0;
    for (int k0 = 0; k0 < K; k0 += BK) {
        const bool hasNext = (k0 + BK < K);
        if (hasNext) load_gmem(k0 + BK);
#pragma unroll
        for (int ks = 0; ks < 2; ks++) {
            const int kk = ks * 8;
            uint32_t ah[4][4], al[4][4], bh[4][2], bl[4][2];
#pragma unroll
            for (int i = 0; i < 4; i++) {
                const int m0 = warpM + i * 16;
#pragma unroll
                for (int f = 0; f < 4; f++) {
                    const int rr = kk + (f >> 1) * 4 + lr;
                    const int mm = m0 + (f & 1) * 8 + lc;
                    const float2 v = *reinterpret_cast<const float2*>(&AS(cur, rr, 2 * mm));
                    ah[i][f] = __float_as_uint(v.x);
                    al[i][f] = __float_as_uint(v.y);
                }
            }
#pragma unroll
            for (int j = 0; j < 4; j++) {
                const int n0 = warpN + j * 8 + lc;
#pragma unroll
                for (int f = 0; f < 2; f++) {
                    const float2 v = *reinterpret_cast<const float2*>(&BS(cur, kk + f * 4 + lr, 2 * n0));
                    bh[j][f] = __float_as_uint(v.x);
                    bl[j][f] = __float_as_uint(v.y);
                }
            }
#pragma unroll
            for (int i = 0; i < 4; i++)
#pragma unroll
                for (int j = 0; j < 4; j++) {
                    MMA_TF32(acc[i][j], ah[i][0], ah[i][1], ah[i][2], ah[i][3], bh[j][0], bh[j][1]);
                    MMA_TF32(acc[i][j], al[i][0], al[i][1], al[i][2], al[i][3], bh[j][0], bh[j][1]);
                    MMA_TF32(acc[i][j], ah[i][0], ah[i][1], ah[i][2], ah[i][3], bl[j][0], bl[j][1]);
                }
        }
        if (hasNext) {
            store_smem(cur ^ 1);
            __syncthreads();
            cur ^= 1;
        }
    }

    float alpha = 1.f;
    if (bwPtr) {
        const float w0 = bwPtr[bwL * 3], w1 = bwPtr[bwL * 3 + 1], w2 = bwPtr[bwL * 3 + 2];
        const float mx = fmaxf(w0, fmaxf(w1, w2));
        const float e0 = expf(w0 - mx), e1 = expf(w1 - mx), e2 = expf(w2 - mx);
        alpha = (z == 0 ? e0 : (z == 1 ? e1 : e2)) / (e0 + e1 + e2);
    }

#pragma unroll
    for (int i = 0; i < 4; i++) {
        const size_t row0 = by * BM + warpM + i * 16 + lc;
#pragma unroll
        for (int j = 0; j < 4; j++) {
            const int col = bx * BN + warpN + j * 8 + lr * 2;
            float2 bv = make_float2(0.f, 0.f);
            if (bias) bv = *reinterpret_cast<const float2*>(bias + col);
            float v00 = (acc[i][j][0] + bv.x) * alpha;
            float v01 = (acc[i][j][1] + bv.y) * alpha;
            float v10 = (acc[i][j][2] + bv.x) * alpha;
            float v11 = (acc[i][j][3] + bv.y) * alpha;
            if (reluFlag) {
                v00 = fmaxf(v00, 0.f); v01 = fmaxf(v01, 0.f);
                v10 = fmaxf(v10, 0.f); v11 = fmaxf(v11, 0.f);
            }
            const uint2 s00 = splitf(v00), s01 = splitf(v01);
            const uint2 s10 = splitf(v10), s11 = splitf(v11);
            *reinterpret_cast<uint4*>(C + row0 * ldc + col) =
                make_uint4(s00.x, s00.y, s01.x, s01.y);
            *reinterpret_cast<uint4*>(C + (row0 + 8) * ldc + col) =
                make_uint4(s10.x, s10.y, s11.x, s11.y);
        }
    }
#undef AS
#undef BS
}

// U[k,i,j] -> eU (same layout) and eUcat[i, k*1024+j]
__global__ void split_U_kernel(const float* __restrict__ U)
{
    const int idx = blockIdx.x * 256 + threadIdx.x;     // 3*1024*1024
    const int k = idx >> 20, i = (idx >> 10) & 1023, j = idx & 1023;
    const uint2 s = splitf(U[idx]);
    eU[idx] = s;
    eUcat[(size_t)i * 3072 + k * 1024 + j] = s;
}

// x[b,j,d] -> eHa[j, b*64+d]
__global__ void split_x_kernel(const float* __restrict__ x)
{
    const int idx = blockIdx.x * 256 + threadIdx.x;     // 4194304
    const int d = idx & 63, b = (idx >> 6) & 63, j = idx >> 12;
    eHa[idx] = splitf(x[(size_t)b * 65536 + (size_t)j * 64 + d]);
}

__global__ void split_w_kernel(const float* __restrict__ w1, int n1,
                               const float* __restrict__ w2, int n2)
{
    const int idx = blockIdx.x * 256 + threadIdx.x;
    if (idx < n1) eW1[idx] = splitf(w1[idx]);
    if (idx < n2) eW2[idx] = splitf(w2[idx]);
}

// pooled[b,d] = mean_i (hi+lo) of eHb[i, b*128+d]
__global__ void pool_kernel()
{
    const int b = blockIdx.x, t = threadIdx.x;
    const int d = t & 127, s = t >> 7;
    float sum = 0.f;
    for (int i = s; i < 1024; i += 4) {
        const uint2 u = eHb[(size_t)i * 8192 + b * 128 + d];
        sum += __uint_as_float(u.x) + __uint_as_float(u.y);
    }
    __shared__ float red[512];
    red[t] = sum;
    __syncthreads();
    if (s == 0)
        g_pooled[b * 128 + d] =
            (red[d] + red[d + 128] + red[d + 256] + red[d + 384]) * (1.f / 1024.f);
}

__global__ void classifier_kernel(const float* __restrict__ Wc1,
                                  const float* __restrict__ bc1,
                                  const float* __restrict__ al,
                                  const float* __restrict__ Wc2,
                                  const float* __restrict__ bc2,
                                  float* __restrict__ out)
{
    __shared__ float zs[64][128];
    const int t = threadIdx.x;
    for (int idx = t; idx < 64 * 128; idx += 256) {
        const int b = idx >> 7, h = idx & 127;
        float acc = bc1[h];
        for (int d = 0; d < 128; d++)
            acc = fmaf(g_pooled[b * 128 + d], Wc1[d * 128 + h], acc);
        zs[b][h] = acc > 0.f ? acc : al[h] * acc;
    }
    __syncthreads();
    const int b = t >> 2, c = t & 3;
    float acc = bc2[c];
    for (int h = 0; h < 128; h++)
        acc = fmaf(zs[b][h], Wc2[h * 4 + c], acc);
    out[b * 4 + c] = acc;
}

// ---------------------------------------------------------------------------
extern "C" void kernel_launch(void* const* d_in, const int* in_sizes, int n_in,
                              void* d_out, int out_size)
{
    const float* x    = (const float*)d_in[0];
    const float* U    = (const float*)d_in[1];
    const float* w1_0 = (const float*)d_in[2];
    const float* b1_0 = (const float*)d_in[3];
    const float* w2_0 = (const float*)d_in[4];
    const float* b2_0 = (const float*)d_in[5];
    const float* w1_r = (const float*)d_in[6];
    const float* b1_r = (const float*)d_in[7];
    const float* w2_r = (const float*)d_in[8];
    const float* b2_r = (const float*)d_in[9];
    const float* bw   = (const float*)d_in[10];
    const float* Wc1  = (const float*)d_in[11];
    const float* bc1  = (const float*)d_in[12];
    const float* alp  = (const float*)d_in[13];
    const float* Wc2  = (const float*)d_in[14];
    const float* bc2  = (const float*)d_in[15];
    float* out = (float*)d_out;

    cudaFuncSetAttribute(gemm_ps, cudaFuncAttributeMaxDynamicSharedMemorySize, SMEM_BYTES);

    split_U_kernel<<<12288, 256>>>(U);
    split_x_kernel<<<16384, 256>>>(x);

    const long long SB = 8388608LL;
    int hinTag = 0, houtTag = 1;
    for (int l = 0; l < 3; l++) {
        const int Din   = (l == 0) ? 64 : 128;
        const int Wcols = 64 * Din;
        const float* w1 = (l == 0) ? w1_0 : (w1_r + (size_t)(l - 1) * 3 * 128 * 128);
        const float* b1 = (l == 0) ? b1_0 : (b1_r + (size_t)(l - 1) * 3 * 128);
        const float* w2 = (l == 0) ? w2_0 : (w2_r + (size_t)(l - 1) * 3 * 128 * 128);
        const float* b2 = (l == 0) ? b2_0 : (b2_r + (size_t)(l - 1) * 3 * 128);

        split_w_kernel<<<192, 256>>>(w1, 3 * Din * 128, w2, 3 * 128 * 128);

        // 1) AGG_k = U_k^T @ H_in
        {
            dim3 g(Wcols / BN, 1024 / BM, 3);
            gemm_ps<<<g, 256, SMEM_BYTES>>>(5, 1048576LL, 1024,
                                            hinTag, 0LL, Wcols,
                                            2, SB, Wcols,
                                            1024, nullptr, 0, nullptr, 0, 1, 0);
        }
        // 2) M1_k = relu(AGG_k @ w1_k + b1_k)
        {
            dim3 g(1, 65536 / BM, 3);
            gemm_ps<<<g, 256, SMEM_BYTES>>>(2, SB, Din,
                                            7, (long long)Din * 128, 128,
                                            3, SB, 128,
                                            Din, b1, 128, nullptr, 0, 0, 1);
        }
        // 3) M2s_k = ws_k * (M1_k @ w2_k + b2_k)
        {
            dim3 g(1, 65536 / BM, 3);
            gemm_ps<<<g, 256, SMEM_BYTES>>>(3, SB, 128,
                                            8, 16384LL, 128,
                                            4, SB, 128,
                                            128, b2, 128, bw, l, 0, 0);
        }
        // 4) H_out = relu(Ucat @ M2_all)  -- single K=3072 GEMM
        {
            dim3 g(8192 / BN, 1024 / BM, 1);
            gemm_ps<<<g, 256, SMEM_BYTES>>>(6, 0LL, 3072,
                                            4, 0LL, 8192,
                                            houtTag, 0LL, 8192,
                                            3072, nullptr, 0, nullptr, 0, 0, 1);
        }
        const int t = hinTag; hinTag = houtTag; houtTag = t;
    }

    // final H in eHb (schedule: out 1, 0, 1)
    pool_kernel<<<64, 512>>>();
    classifier_kernel<<<1, 256>>>(Wc1, bc1, alp, Wc2, bc2, out);
}

// round 8
// speedup vs baseline: 1.4481x; 1.4481x over previous
#include <cuda_runtime.h>
#include <cuda_fp16.h>
#include <cstdint>

// B=64, N=1024, DIN=64, DH=128, H_MLP=128, L=3, C=4
// fp16-pair GEMM: A word = half2(ha,la); B words w1=(hb,hb), w2=(lb,0).
// Two m16n8k16 MMAs give ha*hb + la*hb + ha*lb. All splits at producer time.

#define PAD 136   // words per smem row (128 + 8)

// A-role buffers (1 word/elem), B-role buffers (uint2/elem)
__device__ uint32_t eU [3u * 1048576u];      // [z][j][i]-as-stored = U[z][j][i]
__device__ uint32_t eUt[3u * 1048576u];      // eUt[z][j][i] = U[z][i][j]
__device__ uint32_t eAGG[3u * 8388608u];
__device__ uint32_t eM1 [3u * 8388608u];
__device__ uint2    eM2 [3072u * 8192u];     // rows z*1024+node, cols b*128+d
__device__ uint2    eHa [1024u * 8192u];
__device__ uint2    eHb [1024u * 8192u];
__device__ uint2    eW1 [3 * 128 * 128];
__device__ uint2    eW2 [3 * 128 * 128];
__device__ float    g_pooled[64 * 128];

__device__ __forceinline__ uint32_t* resolveA(int t) {
    switch (t) { case 0: return eU; case 1: return eUt; case 2: return eAGG; default: return eM1; }
}
__device__ __forceinline__ uint2* resolveB(int t) {
    switch (t) { case 0: return eHa; case 1: return eHb; case 2: return eW1;
                 case 3: return eW2; default: return eM2; }
}

__device__ __forceinline__ uint32_t packA(float v) {
    __half h = __float2half_rn(v);
    __half l = __float2half_rn(v - __half2float(h));
    return (uint32_t)__half_as_ushort(h) | ((uint32_t)__half_as_ushort(l) << 16);
}
__device__ __forceinline__ uint2 packB(float v) {
    __half h = __float2half_rn(v);
    __half l = __float2half_rn(v - __half2float(h));
    const uint32_t hb = (uint32_t)__half_as_ushort(h);
    const uint32_t lb = (uint32_t)__half_as_ushort(l);
    return make_uint2(hb | (hb << 16), lb);
}
__device__ __forceinline__ float unpackB(uint2 w) {
    return __half2float(__ushort_as_half((unsigned short)(w.x & 0xFFFF)))
         + __half2float(__ushort_as_half((unsigned short)(w.y & 0xFFFF)));
}

#define MMA16(d, a, b0, b1)                                                   \
    asm volatile(                                                             \
        "mma.sync.aligned.m16n8k16.row.col.f32.f16.f16.f32 "                  \
        "{%0,%1,%2,%3},{%4,%5,%6,%7},{%8,%9},{%0,%1,%2,%3};"                  \
        : "+f"(d[0]), "+f"(d[1]), "+f"(d[2]), "+f"(d[3])                      \
        : "r"(a[0]), "r"(a[1]), "r"(a[2]), "r"(a[3]), "r"(b0), "r"(b1))

#define STG_F (16 * PAD)
#define SMEM_BYTES (6 * STG_F * 4)            // A[2] + B1[2] + B2[2]

// ---------------------------------------------------------------------------
__global__ void __launch_bounds__(256, 1)
gemm_h(int aTag, long long aZ, int lda, int transA,
       int bTag, long long bZ, int ldb,
       int oTag, long long oZ, int ldc, int outMode,
       int K, const float* __restrict__ bias, int biasZ,
       const float* __restrict__ bwPtr, int bwL, int reluFlag)
{
    extern __shared__ uint32_t smw[];
    uint32_t* sA  = smw;                      // [2][16][PAD]
    uint32_t* sB1 = smw + 2 * STG_F;
    uint32_t* sB2 = smw + 4 * STG_F;
#define AS(st, r, c)  sA [(st) * STG_F + (r) * PAD + (c)]
#define B1(st, r, c)  sB1[(st) * STG_F + (r) * PAD + (c)]
#define B2(st, r, c)  sB2[(st) * STG_F + (r) * PAD + (c)]

    const int z = blockIdx.z, bx = blockIdx.x, by = blockIdx.y;
    const uint32_t* A = resolveA(aTag) + (long long)z * aZ;
    const uint2*    B = resolveB(bTag) + (long long)z * bZ;
    if (bias) bias += z * biasZ;

    const int tid = threadIdx.x, warp = tid >> 5, lane = tid & 31;
    const int warpM = (warp >> 2) * 64, warpN = (warp & 3) * 32;
    const int c4 = lane & 3, g = lane >> 2;

    const int ldR = tid >> 5, ldC = (tid & 31) * 4;   // trans-A loader
    const int am  = tid >> 1, akq = (tid & 1) * 8;    // non-trans A scatter
    const int br  = tid >> 4, bc = (tid & 15) * 8;    // B loader

    float acc[4][4][4];
#pragma unroll
    for (int i = 0; i < 4; i++)
#pragma unroll
        for (int j = 0; j < 4; j++)
#pragma unroll
            for (int r = 0; r < 4; r++) acc[i][j][r] = 0.f;

    uint4 rA0, rA1, rB[4];
    auto load_gmem = [&](int k0) {
        if (transA) {
            rA0 = *reinterpret_cast<const uint4*>(A + (size_t)(k0 + ldR)     * lda + by * 128 + ldC);
            rA1 = *reinterpret_cast<const uint4*>(A + (size_t)(k0 + ldR + 8) * lda + by * 128 + ldC);
        } else {
            rA0 = *reinterpret_cast<const uint4*>(A + (size_t)(by * 128 + am) * lda + k0 + akq);
            rA1 = *reinterpret_cast<const uint4*>(A + (size_t)(by * 128 + am) * lda + k0 + akq + 4);
        }
#pragma unroll
        for (int q = 0; q < 4; q++)
            rB[q] = *reinterpret_cast<const uint4*>(B + (size_t)(k0 + br) * ldb + bx * 128 + bc + 2 * q);
    };
    auto store_smem = [&](int st) {
        if (transA) {
            *reinterpret_cast<uint4*>(&AS(st, ldR, ldC))     = rA0;
            *reinterpret_cast<uint4*>(&AS(st, ldR + 8, ldC)) = rA1;
        } else {
            const uint32_t* p0 = reinterpret_cast<const uint32_t*>(&rA0);
            const uint32_t* p1 = reinterpret_cast<const uint32_t*>(&rA1);
#pragma unroll
            for (int q = 0; q < 4; q++) {
                AS(st, akq + q, am)     = p0[q];
                AS(st, akq + 4 + q, am) = p1[q];
            }
        }
#pragma unroll
        for (int q = 0; q < 4; q++) {
            *reinterpret_cast<uint2*>(&B1(st, br, bc + 2 * q)) = make_uint2(rB[q].x, rB[q].z);
            *reinterpret_cast<uint2*>(&B2(st, br, bc + 2 * q)) = make_uint2(rB[q].y, rB[q].w);
        }
    };

    load_gmem(0);
    store_smem(0);
    __syncthreads();

    int cur = 0;
    for (int k0 = 0; k0 < K; k0 += 16) {
        const bool hasNext = (k0 + 16 < K);
        if (hasNext) load_gmem(k0 + 16);
#pragma unroll
        for (int s = 0; s < 2; s++) {
            const int kw = s * 8 + c4;
            uint32_t a[4][4], p[4][2], q[4][2];
#pragma unroll
            for (int i = 0; i < 4; i++) {
                const int m = warpM + i * 16 + g;
                a[i][0] = AS(cur, kw, m);     a[i][1] = AS(cur, kw, m + 8);
                a[i][2] = AS(cur, kw + 4, m); a[i][3] = AS(cur, kw + 4, m + 8);
            }
#pragma unroll
            for (int j = 0; j < 4; j++) {
                const int n = warpN + j * 8 + g;
                p[j][0] = B1(cur, kw, n); p[j][1] = B1(cur, kw + 4, n);
                q[j][0] = B2(cur, kw, n); q[j][1] = B2(cur, kw + 4, n);
            }
#pragma unroll
            for (int i = 0; i < 4; i++)
#pragma unroll
                for (int j = 0; j < 4; j++) {
                    MMA16(acc[i][j], a[i], p[j][0], p[j][1]);
                    MMA16(acc[i][j], a[i], q[j][0], q[j][1]);
                }
        }
        if (hasNext) { store_smem(cur ^ 1); __syncthreads(); cur ^= 1; }
    }

    float alpha = 1.f;
    if (bwPtr) {
        const float w0 = bwPtr[bwL * 3], w1 = bwPtr[bwL * 3 + 1], w2 = bwPtr[bwL * 3 + 2];
        const float mx = fmaxf(w0, fmaxf(w1, w2));
        const float e0 = expf(w0 - mx), e1 = expf(w1 - mx), e2 = expf(w2 - mx);
        alpha = (z == 0 ? e0 : (z == 1 ? e1 : e2)) / (e0 + e1 + e2);
    }

    uint32_t* OA = resolveA(oTag) + (long long)z * oZ;
    uint2*    OB = resolveB(oTag) + (long long)z * oZ;
#pragma unroll
    for (int i = 0; i < 4; i++) {
#pragma unroll
        for (int half = 0; half < 2; half++) {
            const int row = by * 128 + warpM + i * 16 + g + half * 8;
#pragma unroll
            for (int j = 0; j < 4; j++) {
                const int col = bx * 128 + warpN + j * 8 + 2 * c4;
                float v0 = acc[i][j][half * 2], v1 = acc[i][j][half * 2 + 1];
                if (bias) {
                    const float2 bv = *reinterpret_cast<const float2*>(bias + col);
                    v0 += bv.x; v1 += bv.y;
                }
                v0 *= alpha; v1 *= alpha;
                if (reluFlag) { v0 = fmaxf(v0, 0.f); v1 = fmaxf(v1, 0.f); }
                if (outMode == 0) {
                    *reinterpret_cast<uint2*>(OA + (size_t)row * ldc + col) =
                        make_uint2(packA(v0), packA(v1));
                } else {
                    size_t off;
                    if (outMode == 1) off = (size_t)row * ldc + col;
                    else off = (size_t)(z * 1024 + (row >> 6)) * 8192 + (row & 63) * 128 + col;
                    const uint2 w0 = packB(v0), w1 = packB(v1);
                    *reinterpret_cast<uint4*>(OB + off) = make_uint4(w0.x, w0.y, w1.x, w1.y);
                }
            }
        }
    }
#undef AS
#undef B1
#undef B2
}

__global__ void split_U_kernel(const float* __restrict__ U)
{
    const int idx = blockIdx.x * 256 + threadIdx.x;   // 3*1024*1024
    eU[idx] = packA(U[idx]);
}
__global__ void transpose_U_kernel(const float* __restrict__ U)
{
    __shared__ float t[32][33];
    const int z = blockIdx.z, i0 = blockIdx.y * 32, j0 = blockIdx.x * 32;
    const int tx = threadIdx.x, ty = threadIdx.y;   // 32 x 8
    for (int yy = 0; yy < 4; yy++)
        t[ty + 8 * yy][tx] = U[(size_t)z * 1048576 + (size_t)(i0 + ty + 8 * yy) * 1024 + j0 + tx];
    __syncthreads();
    for (int yy = 0; yy < 4; yy++)
        eUt[(size_t)z * 1048576 + (size_t)(j0 + ty + 8 * yy) * 1024 + i0 + tx] =
            packA(t[tx][ty + 8 * yy]);
}
__global__ void split_x_kernel(const float* __restrict__ x)
{
    const int idx = blockIdx.x * 256 + threadIdx.x;   // 4194304
    const int d = idx & 63, b = (idx >> 6) & 63, j = idx >> 12;
    eHa[(size_t)j * 4096 + b * 64 + d] = packB(x[(size_t)b * 65536 + (size_t)j * 64 + d]);
}
__global__ void split_w_kernel(const float* __restrict__ w1, int n1,
                               const float* __restrict__ w2, int n2)
{
    const int idx = blockIdx.x * 256 + threadIdx.x;
    if (idx < n1) eW1[idx] = packB(w1[idx]);
    if (idx < n2) eW2[idx] = packB(w2[idx]);
}

__global__ void pool_kernel()
{
    const int b = blockIdx.x, t = threadIdx.x;
    const int d = t & 127, s = t >> 7;
    float sum = 0.f;
    for (int i = s; i < 1024; i += 4)
        sum += unpackB(eHb[(size_t)i * 8192 + b * 128 + d]);
    __shared__ float red[512];
    red[t] = sum;
    __syncthreads();
    if (s == 0)
        g_pooled[b * 128 + d] =
            (red[d] + red[d + 128] + red[d + 256] + red[d + 384]) * (1.f / 1024.f);
}

__global__ void classifier_kernel(const float* __restrict__ Wc1,
                                  const float* __restrict__ bc1,
                                  const float* __restrict__ al,
                                  const float* __restrict__ Wc2,
                                  const float* __restrict__ bc2,
                                  float* __restrict__ out)
{
    __shared__ float zs[64][128];
    const int t = threadIdx.x;
    for (int idx = t; idx < 64 * 128; idx += 256) {
        const int b = idx >> 7, h = idx & 127;
        float acc = bc1[h];
        for (int d = 0; d < 128; d++)
            acc = fmaf(g_pooled[b * 128 + d], Wc1[d * 128 + h], acc);
        zs[b][h] = acc > 0.f ? acc : al[h] * acc;
    }
    __syncthreads();
    const int b = t >> 2, c = t & 3;
    float acc = bc2[c];
    for (int h = 0; h < 128; h++)
        acc = fmaf(zs[b][h], Wc2[h * 4 + c], acc);
    out[b * 4 + c] = acc;
}

// ---------------------------------------------------------------------------
extern "C" void kernel_launch(void* const* d_in, const int* in_sizes, int n_in,
                              void* d_out, int out_size)
{
    const float* x    = (const float*)d_in[0];
    const float* U    = (const float*)d_in[1];
    const float* w1_0 = (const float*)d_in[2];
    const float* b1_0 = (const float*)d_in[3];
    const float* w2_0 = (const float*)d_in[4];
    const float* b2_0 = (const float*)d_in[5];
    const float* w1_r = (const float*)d_in[6];
    const float* b1_r = (const float*)d_in[7];
    const float* w2_r = (const float*)d_in[8];
    const float* b2_r = (const float*)d_in[9];
    const float* bw   = (const float*)d_in[10];
    const float* Wc1  = (const float*)d_in[11];
    const float* bc1  = (const float*)d_in[12];
    const float* alp  = (const float*)d_in[13];
    const float* Wc2  = (const float*)d_in[14];
    const float* bc2  = (const float*)d_in[15];
    float* out = (float*)d_out;

    cudaFuncSetAttribute(gemm_h, cudaFuncAttributeMaxDynamicSharedMemorySize, SMEM_BYTES);

    split_U_kernel<<<12288, 256>>>(U);
    transpose_U_kernel<<<dim3(32, 32, 3), dim3(32, 8)>>>(U);
    split_x_kernel<<<16384, 256>>>(x);

    int hinTag = 0, houtTag = 1;
    for (int l = 0; l < 3; l++) {
        const int Din   = (l == 0) ? 64 : 128;
        const int Wcols = 64 * Din;
        const float* w1 = (l == 0) ? w1_0 : (w1_r + (size_t)(l - 1) * 3 * 128 * 128);
        const float* b1 = (l == 0) ? b1_0 : (b1_r + (size_t)(l - 1) * 3 * 128);
        const float* w2 = (l == 0) ? w2_0 : (w2_r + (size_t)(l - 1) * 3 * 128 * 128);
        const float* b2 = (l == 0) ? b2_0 : (b2_r + (size_t)(l - 1) * 3 * 128);

        split_w_kernel<<<192, 256>>>(w1, 3 * Din * 128, w2, 3 * 128 * 128);

        // 1) AGG_z = U_z^T @ H   -> eAGG (A-role), per-branch stride 8388608
        gemm_h<<<dim3(Wcols / 128, 8, 3), 256, SMEM_BYTES>>>(
            0, 1048576LL, 1024, 1,
            hinTag, 0LL, Wcols,
            2, 8388608LL, Wcols, 0,
            1024, nullptr, 0, nullptr, 0, 0);
        // 2) M1_z = relu(AGG_z @ w1_z + b1_z) -> eM1 (A-role)
        gemm_h<<<dim3(1, 512, 3), 256, SMEM_BYTES>>>(
            2, 8388608LL, Din, 0,
            2, (long long)Din * 128, 128,
            3, 8388608LL, 128, 0,
            Din, b1, 128, nullptr, 0, 1);
        // 3) M2_z = ws_z * (M1_z @ w2_z + b2_z)  (scatter handles z itself)
        gemm_h<<<dim3(1, 512, 3), 256, SMEM_BYTES>>>(
            3, 8388608LL, 128, 0,
            3, 16384LL, 128,
            4, 0LL, 0, 2,
            128, b2, 128, bw, l, 0);
        // 4) H_out = relu( Ucat @ M2_all ), single K=3072 GEMM
        gemm_h<<<dim3(64, 8, 1), 256, SMEM_BYTES>>>(
            1, 0LL, 1024, 1,
            4, 0LL, 8192,
            houtTag, 0LL, 8192, 1,
            3072, nullptr, 0, nullptr, 0, 1);

        const int t = hinTag; hinTag = houtTag; houtTag = t;
    }

    // final H in eHb (out tags: 1, 0, 1)
    pool_kernel<<<64, 512>>>();
    classifier_kernel<<<1, 256>>>(Wc1, bc1, alp, Wc2, bc2, out);
}

// round 9
// speedup vs baseline: 1.9370x; 1.3376x over previous
#include <cuda_runtime.h>
#include <cuda_fp16.h>
#include <cstdint>

// fp16-pair GEMM, B stored as 2 gmem planes -> verbatim cp.async copies.
// MMA1: A(ha,la) x (hb,hb); MMA2: A x (lb,0) => ha*hb + la*hb + ha*lb.

#define PAD 136
#define STG_F (16 * PAD)
#define SMEM_BYTES (6 * STG_F * 4)

// A-role (1 word/elem)
__device__ uint32_t eU  [3u * 1048576u];
__device__ uint32_t eUt [3u * 1048576u];
__device__ uint32_t eAGG[3u * 8388608u];
__device__ uint32_t eM1 [3u * 8388608u];
// B-role: [plane0 | plane1]
__device__ uint32_t eHa [2u * 8388608u];     // plane stride 8388608
__device__ uint32_t eHb [2u * 8388608u];
__device__ uint32_t eM2 [2u * 25165824u];    // plane stride 25165824
__device__ uint32_t eW1 [2u * 49152u];       // plane stride 49152
__device__ uint32_t eW2 [2u * 49152u];
__device__ float    g_pooled[64 * 128];

__device__ __forceinline__ uint32_t* resolveA(int t) {
    switch (t) { case 0: return eU; case 1: return eUt; case 2: return eAGG; default: return eM1; }
}
__device__ __forceinline__ uint32_t* resolveB(int t) {
    switch (t) { case 0: return eHa; case 1: return eHb; case 2: return eW1;
                 case 3: return eW2; default: return eM2; }
}

__device__ __forceinline__ uint32_t packA(float v) {
    __half h = __float2half_rn(v);
    __half l = __float2half_rn(v - __half2float(h));
    return (uint32_t)__half_as_ushort(h) | ((uint32_t)__half_as_ushort(l) << 16);
}
__device__ __forceinline__ void packB2(float v, uint32_t& w1, uint32_t& w2) {
    __half h = __float2half_rn(v);
    __half l = __float2half_rn(v - __half2float(h));
    const uint32_t hb = (uint32_t)__half_as_ushort(h);
    w1 = hb | (hb << 16);
    w2 = (uint32_t)__half_as_ushort(l);
}

__device__ __forceinline__ uint32_t sm2u(const void* p) {
    return (uint32_t)__cvta_generic_to_shared(p);
}
#define CP16(dst, src) \
    asm volatile("cp.async.cg.shared.global [%0], [%1], 16;" :: "r"(dst), "l"(src))
#define CP_COMMIT() asm volatile("cp.async.commit_group;")
#define CP_WAIT0()  asm volatile("cp.async.wait_group 0;")

#define MMA16(d, a, b0, b1)                                                   \
    asm volatile(                                                             \
        "mma.sync.aligned.m16n8k16.row.col.f32.f16.f16.f32 "                  \
        "{%0,%1,%2,%3},{%4,%5,%6,%7},{%8,%9},{%0,%1,%2,%3};"                  \
        : "+f"(d[0]), "+f"(d[1]), "+f"(d[2]), "+f"(d[3])                      \
        : "r"(a[0]), "r"(a[1]), "r"(a[2]), "r"(a[3]), "r"(b0), "r"(b1))

// ---------------------------------------------------------------------------
__global__ void __launch_bounds__(256, 2)
gemm_h(int aTag, long long aZ, int lda, int transA,
       int bTag, long long bZ, long long bPlane, int ldb,
       int oTag, long long oZ, long long oPlane, int ldc, int outMode,
       int K, const float* __restrict__ bias, int biasZ,
       const float* __restrict__ bwPtr, int bwL, int reluFlag)
{
    extern __shared__ uint32_t smw[];
    uint32_t* sA  = smw;
    uint32_t* sB1 = smw + 2 * STG_F;
    uint32_t* sB2 = smw + 4 * STG_F;
#define AS(st, r, c)  sA [(st) * STG_F + (r) * PAD + (c)]
#define B1(st, r, c)  sB1[(st) * STG_F + (r) * PAD + (c)]
#define B2(st, r, c)  sB2[(st) * STG_F + (r) * PAD + (c)]

    const int z = blockIdx.z, bx = blockIdx.x, by = blockIdx.y;
    const uint32_t* A   = resolveA(aTag) + (long long)z * aZ;
    const uint32_t* Bp0 = resolveB(bTag) + (long long)z * bZ;
    const uint32_t* Bp1 = Bp0 + bPlane;
    if (bias) bias += z * biasZ;

    const int tid = threadIdx.x, warp = tid >> 5, lane = tid & 31;
    const int warpM = (warp >> 2) * 64, warpN = (warp & 3) * 32;
    const int c4 = lane & 3, g = lane >> 2;

    const int ldR = tid >> 5, ldC = (tid & 31) * 4;   // 16B chunk loaders
    const int am  = tid >> 1, akq = (tid & 1) * 8;    // non-trans A scatter

    float acc[4][4][4];
#pragma unroll
    for (int i = 0; i < 4; i++)
#pragma unroll
        for (int j = 0; j < 4; j++)
#pragma unroll
            for (int r = 0; r < 4; r++) acc[i][j][r] = 0.f;

    auto issue_stage = [&](int k0, int st) {
        // B planes: 2 chunks per thread per plane
#pragma unroll
        for (int h = 0; h < 2; h++) {
            const int idx = tid + h * 256;
            const int r = idx >> 5, c = (idx & 31) * 4;
            const size_t go = (size_t)(k0 + r) * ldb + bx * 128 + c;
            CP16(sm2u(&B1(st, r, c)), Bp0 + go);
            CP16(sm2u(&B2(st, r, c)), Bp1 + go);
        }
        if (transA) {
            CP16(sm2u(&AS(st, ldR, c4 * 0 + ldC)),
                 A + (size_t)(k0 + ldR) * lda + by * 128 + ldC);
            CP16(sm2u(&AS(st, ldR + 8, ldC)),
                 A + (size_t)(k0 + ldR + 8) * lda + by * 128 + ldC);
        } else {
            const uint4 r0 = *reinterpret_cast<const uint4*>(
                A + (size_t)(by * 128 + am) * lda + k0 + akq);
            const uint4 r1 = *reinterpret_cast<const uint4*>(
                A + (size_t)(by * 128 + am) * lda + k0 + akq + 4);
            const uint32_t* p0 = reinterpret_cast<const uint32_t*>(&r0);
            const uint32_t* p1 = reinterpret_cast<const uint32_t*>(&r1);
#pragma unroll
            for (int q = 0; q < 4; q++) {
                AS(st, akq + q, am)     = p0[q];
                AS(st, akq + 4 + q, am) = p1[q];
            }
        }
        CP_COMMIT();
    };

    issue_stage(0, 0);

    int cur = 0;
    for (int k0 = 0; k0 < K; k0 += 16) {
        CP_WAIT0();
        __syncthreads();
        if (k0 + 16 < K) issue_stage(k0 + 16, cur ^ 1);
#pragma unroll
        for (int s = 0; s < 2; s++) {
            const int kw = s * 8 + c4;
            uint32_t a[4][4], p[4][2], q[4][2];
#pragma unroll
            for (int i = 0; i < 4; i++) {
                const int m = warpM + i * 16 + g;
                a[i][0] = AS(cur, kw, m);     a[i][1] = AS(cur, kw, m + 8);
                a[i][2] = AS(cur, kw + 4, m); a[i][3] = AS(cur, kw + 4, m + 8);
            }
#pragma unroll
            for (int j = 0; j < 4; j++) {
                const int n = warpN + j * 8 + g;
                p[j][0] = B1(cur, kw, n); p[j][1] = B1(cur, kw + 4, n);
                q[j][0] = B2(cur, kw, n); q[j][1] = B2(cur, kw + 4, n);
            }
#pragma unroll
            for (int i = 0; i < 4; i++)
#pragma unroll
                for (int j = 0; j < 4; j++) {
                    MMA16(acc[i][j], a[i], p[j][0], p[j][1]);
                    MMA16(acc[i][j], a[i], q[j][0], q[j][1]);
                }
        }
        cur ^= 1;
        __syncthreads();
    }

    float alpha = 1.f;
    if (bwPtr) {
        const float w0 = bwPtr[bwL * 3], w1 = bwPtr[bwL * 3 + 1], w2 = bwPtr[bwL * 3 + 2];
        const float mx = fmaxf(w0, fmaxf(w1, w2));
        const float e0 = expf(w0 - mx), e1 = expf(w1 - mx), e2 = expf(w2 - mx);
        alpha = (z == 0 ? e0 : (z == 1 ? e1 : e2)) / (e0 + e1 + e2);
    }

    uint32_t* OA = resolveA(oTag) + (long long)z * oZ;
    uint32_t* O0 = resolveB(oTag) + (long long)z * oZ;
    uint32_t* O1 = O0 + oPlane;
#pragma unroll
    for (int i = 0; i < 4; i++) {
#pragma unroll
        for (int half = 0; half < 2; half++) {
            const int row = by * 128 + warpM + i * 16 + g + half * 8;
#pragma unroll
            for (int j = 0; j < 4; j++) {
                const int col = bx * 128 + warpN + j * 8 + 2 * c4;
                float v0 = acc[i][j][half * 2], v1 = acc[i][j][half * 2 + 1];
                if (bias) {
                    const float2 bv = *reinterpret_cast<const float2*>(bias + col);
                    v0 += bv.x; v1 += bv.y;
                }
                v0 *= alpha; v1 *= alpha;
                if (reluFlag) { v0 = fmaxf(v0, 0.f); v1 = fmaxf(v1, 0.f); }
                if (outMode == 0) {
                    *reinterpret_cast<uint2*>(OA + (size_t)row * ldc + col) =
                        make_uint2(packA(v0), packA(v1));
                } else {
                    size_t off;
                    if (outMode == 1) off = (size_t)row * ldc + col;
                    else off = (size_t)(z * 1024 + (row >> 6)) * 8192 + (row & 63) * 128 + col;
                    uint32_t w10, w20, w11, w21;
                    packB2(v0, w10, w20);
                    packB2(v1, w11, w21);
                    *reinterpret_cast<uint2*>(O0 + off) = make_uint2(w10, w11);
                    *reinterpret_cast<uint2*>(O1 + off) = make_uint2(w20, w21);
                }
            }
        }
    }
#undef AS
#undef B1
#undef B2
}

__global__ void split_U_kernel(const float* __restrict__ U)
{
    const int idx = blockIdx.x * 256 + threadIdx.x;
    eU[idx] = packA(U[idx]);
}
__global__ void transpose_U_kernel(const float* __restrict__ U)
{
    __shared__ float t[32][33];
    const int z = blockIdx.z, i0 = blockIdx.y * 32, j0 = blockIdx.x * 32;
    const int tx = threadIdx.x, ty = threadIdx.y;
    for (int yy = 0; yy < 4; yy++)
        t[ty + 8 * yy][tx] = U[(size_t)z * 1048576 + (size_t)(i0 + ty + 8 * yy) * 1024 + j0 + tx];
    __syncthreads();
    for (int yy = 0; yy < 4; yy++)
        eUt[(size_t)z * 1048576 + (size_t)(j0 + ty + 8 * yy) * 1024 + i0 + tx] =
            packA(t[tx][ty + 8 * yy]);
}
__global__ void split_x_kernel(const float* __restrict__ x)
{
    const int idx = blockIdx.x * 256 + threadIdx.x;
    const int d = idx & 63, b = (idx >> 6) & 63, j = idx >> 12;
    uint32_t w1, w2;
    packB2(x[(size_t)b * 65536 + (size_t)j * 64 + d], w1, w2);
    const size_t off = (size_t)j * 4096 + b * 64 + d;
    eHa[off] = w1;
    eHa[8388608u + off] = w2;
}
__global__ void split_w_kernel(const float* __restrict__ w1, int n1,
                               const float* __restrict__ w2, int n2)
{
    const int idx = blockIdx.x * 256 + threadIdx.x;
    uint32_t a, b;
    if (idx < n1) { packB2(w1[idx], a, b); eW1[idx] = a; eW1[49152u + idx] = b; }
    if (idx < n2) { packB2(w2[idx], a, b); eW2[idx] = a; eW2[49152u + idx] = b; }
}

__global__ void pool_kernel()
{
    const int b = blockIdx.x, t = threadIdx.x;
    const int d = t & 127, s = t >> 7;
    float sum = 0.f;
    for (int i = s; i < 1024; i += 4) {
        const size_t off = (size_t)i * 8192 + b * 128 + d;
        sum += __half2float(__ushort_as_half((unsigned short)(eHb[off] & 0xFFFF)))
             + __half2float(__ushort_as_half((unsigned short)(eHb[8388608u + off] & 0xFFFF)));
    }
    __shared__ float red[512];
    red[t] = sum;
    __syncthreads();
    if (s == 0)
        g_pooled[b * 128 + d] =
            (red[d] + red[d + 128] + red[d + 256] + red[d + 384]) * (1.f / 1024.f);
}

__global__ void classifier_kernel(const float* __restrict__ Wc1,
                                  const float* __restrict__ bc1,
                                  const float* __restrict__ al,
                                  const float* __restrict__ Wc2,
                                  const float* __restrict__ bc2,
                                  float* __restrict__ out)
{
    __shared__ float zs[64][128];
    const int t = threadIdx.x;
    for (int idx = t; idx < 64 * 128; idx += 256) {
        const int b = idx >> 7, h = idx & 127;
        float acc = bc1[h];
        for (int d = 0; d < 128; d++)
            acc = fmaf(g_pooled[b * 128 + d], Wc1[d * 128 + h], acc);
        zs[b][h] = acc > 0.f ? acc : al[h] * acc;
    }
    __syncthreads();
    const int b = t >> 2, c = t & 3;
    float acc = bc2[c];
    for (int h = 0; h < 128; h++)
        acc = fmaf(zs[b][h], Wc2[h * 4 + c], acc);
    out[b * 4 + c] = acc;
}

// ---------------------------------------------------------------------------
extern "C" void kernel_launch(void* const* d_in, const int* in_sizes, int n_in,
                              void* d_out, int out_size)
{
    const float* x    = (const float*)d_in[0];
    const float* U    = (const float*)d_in[1];
    const float* w1_0 = (const float*)d_in[2];
    const float* b1_0 = (const float*)d_in[3];
    const float* w2_0 = (const float*)d_in[4];
    const float* b2_0 = (const float*)d_in[5];
    const float* w1_r = (const float*)d_in[6];
    const float* b1_r = (const float*)d_in[7];
    const float* w2_r = (const float*)d_in[8];
    const float* b2_r = (const float*)d_in[9];
    const float* bw   = (const float*)d_in[10];
    const float* Wc1  = (const float*)d_in[11];
    const float* bc1  = (const float*)d_in[12];
    const float* alp  = (const float*)d_in[13];
    const float* Wc2  = (const float*)d_in[14];
    const float* bc2  = (const float*)d_in[15];
    float* out = (float*)d_out;

    cudaFuncSetAttribute(gemm_h, cudaFuncAttributeMaxDynamicSharedMemorySize, SMEM_BYTES);

    split_U_kernel<<<12288, 256>>>(U);
    transpose_U_kernel<<<dim3(32, 32, 3), dim3(32, 8)>>>(U);
    split_x_kernel<<<16384, 256>>>(x);

    int hinTag = 0, houtTag = 1;
    for (int l = 0; l < 3; l++) {
        const int Din   = (l == 0) ? 64 : 128;
        const int Wcols = 64 * Din;
        const float* w1 = (l == 0) ? w1_0 : (w1_r + (size_t)(l - 1) * 3 * 128 * 128);
        const float* b1 = (l == 0) ? b1_0 : (b1_r + (size_t)(l - 1) * 3 * 128);
        const float* w2 = (l == 0) ? w2_0 : (w2_r + (size_t)(l - 1) * 3 * 128 * 128);
        const float* b2 = (l == 0) ? b2_0 : (b2_r + (size_t)(l - 1) * 3 * 128);

        split_w_kernel<<<192, 256>>>(w1, 3 * Din * 128, w2, 3 * 128 * 128);

        // 1) AGG_z = U_z^T @ H -> eAGG (A-role)
        gemm_h<<<dim3(Wcols / 128, 8, 3), 256, SMEM_BYTES>>>(
            0, 1048576LL, 1024, 1,
            hinTag, 0LL, 8388608LL, Wcols,
            2, 8388608LL, 0LL, Wcols, 0,
            1024, nullptr, 0, nullptr, 0, 0);
        // 2) M1_z = relu(AGG_z @ w1_z + b1_z) -> eM1 (A-role)
        gemm_h<<<dim3(1, 512, 3), 256, SMEM_BYTES>>>(
            2, 8388608LL, Din, 0,
            2, (long long)Din * 128, 49152LL, 128,
            3, 8388608LL, 0LL, 128, 0,
            Din, b1, 128, nullptr, 0, 1);
        // 3) M2_z = ws_z * (M1_z @ w2_z + b2_z) -> eM2 scatter (B-role)
        gemm_h<<<dim3(1, 512, 3), 256, SMEM_BYTES>>>(
            3, 8388608LL, 128, 0,
            3, 16384LL, 49152LL, 128,
            4, 0LL, 25165824LL, 0, 2,
            128, b2, 128, bw, l, 0);
        // 4) H_out = relu(Ucat @ M2_all), single K=3072 GEMM
        gemm_h<<<dim3(64, 8, 1), 256, SMEM_BYTES>>>(
            1, 0LL, 1024, 1,
            4, 0LL, 25165824LL, 8192,
            houtTag, 0LL, 8388608LL, 8192, 1,
            3072, nullptr, 0, nullptr, 0, 1);

        const int t = hinTag; hinTag = houtTag; houtTag = t;
    }

    pool_kernel<<<64, 512>>>();
    classifier_kernel<<<1, 256>>>(Wc1, bc1, alp, Wc2, bc2, out);
}

// round 10
// speedup vs baseline: 1.9512x; 1.0074x over previous
#include <cuda_runtime.h>
#include <cuda_fp16.h>
#include <cstdint>

// fp16-pair GEMM, 4-stage cp.async ring.
// MMA1: A(ha,la) x (hb,hb); MMA2: A x (lb,lb) => (ha+la)*(hb+lb) exact-ish.

#define PAD 136
#define STG_F (16 * PAD)
#define NSTG 4
#define SMEM_BYTES (3 * NSTG * STG_F * 4)   // 104448

// A-role (1 word/elem)
__device__ uint32_t eU  [3u * 1048576u];
__device__ uint32_t eUt [3u * 1048576u];
__device__ uint32_t eAGG[3u * 8388608u];
__device__ uint32_t eM1 [3u * 8388608u];
// B-role: [plane0 | plane1]
__device__ uint32_t eHa [2u * 8388608u];     // plane stride 8388608
__device__ uint32_t eHb [2u * 8388608u];
__device__ uint32_t eM2 [2u * 25165824u];    // plane stride 25165824
__device__ uint32_t eW1 [2u * 49152u];       // plane stride 49152
__device__ uint32_t eW2 [2u * 49152u];
__device__ float    g_pooled[64 * 128];

__device__ __forceinline__ uint32_t* resolveA(int t) {
    switch (t) { case 0: return eU; case 1: return eUt; case 2: return eAGG; default: return eM1; }
}
__device__ __forceinline__ uint32_t* resolveB(int t) {
    switch (t) { case 0: return eHa; case 1: return eHb; case 2: return eW1;
                 case 3: return eW2; default: return eM2; }
}

__device__ __forceinline__ uint32_t packA(float v) {
    __half h = __float2half_rn(v);
    __half l = __float2half_rn(v - __half2float(h));
    return (uint32_t)__half_as_ushort(h) | ((uint32_t)__half_as_ushort(l) << 16);
}
__device__ __forceinline__ void packB2(float v, uint32_t& w1, uint32_t& w2) {
    __half h = __float2half_rn(v);
    __half l = __float2half_rn(v - __half2float(h));
    const uint32_t hb = (uint32_t)__half_as_ushort(h);
    const uint32_t lb = (uint32_t)__half_as_ushort(l);
    w1 = hb | (hb << 16);
    w2 = lb | (lb << 16);
}

__device__ __forceinline__ uint32_t sm2u(const void* p) {
    return (uint32_t)__cvta_generic_to_shared(p);
}
#define CP16(dst, src) \
    asm volatile("cp.async.cg.shared.global [%0], [%1], 16;" :: "r"(dst), "l"(src))
#define CP_COMMIT() asm volatile("cp.async.commit_group;")
#define CP_WAIT2()  asm volatile("cp.async.wait_group 2;")

#define MMA16(d, a, b0, b1)                                                   \
    asm volatile(                                                             \
        "mma.sync.aligned.m16n8k16.row.col.f32.f16.f16.f32 "                  \
        "{%0,%1,%2,%3},{%4,%5,%6,%7},{%8,%9},{%0,%1,%2,%3};"                  \
        : "+f"(d[0]), "+f"(d[1]), "+f"(d[2]), "+f"(d[3])                      \
        : "r"(a[0]), "r"(a[1]), "r"(a[2]), "r"(a[3]), "r"(b0), "r"(b1))

// ---------------------------------------------------------------------------
__global__ void __launch_bounds__(256, 2)
gemm_h(int aTag, long long aZ, int lda, int transA,
       int bTag, long long bZ, long long bPlane, int ldb,
       int oTag, long long oZ, long long oPlane, int ldc, int outMode,
       int K, const float* __restrict__ bias, int biasZ,
       const float* __restrict__ bwPtr, int bwL, int reluFlag)
{
    extern __shared__ uint32_t smw[];
    uint32_t* sA  = smw;
    uint32_t* sB1 = smw + NSTG * STG_F;
    uint32_t* sB2 = smw + 2 * NSTG * STG_F;
#define AS(st, r, c)  sA [(st) * STG_F + (r) * PAD + (c)]
#define B1(st, r, c)  sB1[(st) * STG_F + (r) * PAD + (c)]
#define B2(st, r, c)  sB2[(st) * STG_F + (r) * PAD + (c)]

    const int z = blockIdx.z, bx = blockIdx.x, by = blockIdx.y;
    const uint32_t* A   = resolveA(aTag) + (long long)z * aZ;
    const uint32_t* Bp0 = resolveB(bTag) + (long long)z * bZ;
    const uint32_t* Bp1 = Bp0 + bPlane;
    if (bias) bias += z * biasZ;

    const int tid = threadIdx.x, warp = tid >> 5, lane = tid & 31;
    const int warpM = (warp >> 2) * 64, warpN = (warp & 3) * 32;
    const int c4 = lane & 3, g = lane >> 2;

    const int ldR = tid >> 5, ldC = (tid & 31) * 4;
    const int am  = tid >> 1, akq = (tid & 1) * 8;

    float acc[4][4][4];
#pragma unroll
    for (int i = 0; i < 4; i++)
#pragma unroll
        for (int j = 0; j < 4; j++)
#pragma unroll
            for (int r = 0; r < 4; r++) acc[i][j][r] = 0.f;

    auto issue_stage = [&](int k0, int st) {
#pragma unroll
        for (int h = 0; h < 2; h++) {
            const int idx = tid + h * 256;
            const int r = idx >> 5, c = (idx & 31) * 4;
            const size_t go = (size_t)(k0 + r) * ldb + bx * 128 + c;
            CP16(sm2u(&B1(st, r, c)), Bp0 + go);
            CP16(sm2u(&B2(st, r, c)), Bp1 + go);
        }
        if (transA) {
            CP16(sm2u(&AS(st, ldR, ldC)),     A + (size_t)(k0 + ldR)     * lda + by * 128 + ldC);
            CP16(sm2u(&AS(st, ldR + 8, ldC)), A + (size_t)(k0 + ldR + 8) * lda + by * 128 + ldC);
        } else {
            const uint4 r0 = *reinterpret_cast<const uint4*>(
                A + (size_t)(by * 128 + am) * lda + k0 + akq);
            const uint4 r1 = *reinterpret_cast<const uint4*>(
                A + (size_t)(by * 128 + am) * lda + k0 + akq + 4);
            const uint32_t* p0 = reinterpret_cast<const uint32_t*>(&r0);
            const uint32_t* p1 = reinterpret_cast<const uint32_t*>(&r1);
#pragma unroll
            for (int q = 0; q < 4; q++) {
                AS(st, akq + q, am)     = p0[q];
                AS(st, akq + 4 + q, am) = p1[q];
            }
        }
        CP_COMMIT();
    };

    // prologue: 3 stages in flight (all GEMMs have K >= 64)
    issue_stage(0, 0);
    issue_stage(16, 1);
    issue_stage(32, 2);

    for (int k0 = 0; k0 < K; k0 += 16) {
        const int cur = (k0 >> 4) & 3;
        CP_WAIT2();                 // oldest pending group (= stage cur) done
        __syncthreads();            // all warps done computing stage cur-1's slot reuse
        if (k0 + 48 < K) issue_stage(k0 + 48, (cur + 3) & 3);
        else             CP_COMMIT();   // keep pending-group count constant
#pragma unroll
        for (int s = 0; s < 2; s++) {
            const int kw = s * 8 + c4;
            uint32_t a[4][4], p[4][2], q[4][2];
#pragma unroll
            for (int i = 0; i < 4; i++) {
                const int m = warpM + i * 16 + g;
                a[i][0] = AS(cur, kw, m);     a[i][1] = AS(cur, kw, m + 8);
                a[i][2] = AS(cur, kw + 4, m); a[i][3] = AS(cur, kw + 4, m + 8);
            }
#pragma unroll
            for (int j = 0; j < 4; j++) {
                const int n = warpN + j * 8 + g;
                p[j][0] = B1(cur, kw, n); p[j][1] = B1(cur, kw + 4, n);
                q[j][0] = B2(cur, kw, n); q[j][1] = B2(cur, kw + 4, n);
            }
#pragma unroll
            for (int i = 0; i < 4; i++)
#pragma unroll
                for (int j = 0; j < 4; j++) {
                    MMA16(acc[i][j], a[i], p[j][0], p[j][1]);
                    MMA16(acc[i][j], a[i], q[j][0], q[j][1]);
                }
        }
        __syncthreads();
    }

    float alpha = 1.f;
    if (bwPtr) {
        const float w0 = bwPtr[bwL * 3], w1 = bwPtr[bwL * 3 + 1], w2 = bwPtr[bwL * 3 + 2];
        const float mx = fmaxf(w0, fmaxf(w1, w2));
        const float e0 = expf(w0 - mx), e1 = expf(w1 - mx), e2 = expf(w2 - mx);
        alpha = (z == 0 ? e0 : (z == 1 ? e1 : e2)) / (e0 + e1 + e2);
    }

    uint32_t* OA = resolveA(oTag) + (long long)z * oZ;
    uint32_t* O0 = resolveB(oTag) + (long long)z * oZ;
    uint32_t* O1 = O0 + oPlane;
#pragma unroll
    for (int i = 0; i < 4; i++) {
#pragma unroll
        for (int half = 0; half < 2; half++) {
            const int row = by * 128 + warpM + i * 16 + g + half * 8;
#pragma unroll
            for (int j = 0; j < 4; j++) {
                const int col = bx * 128 + warpN + j * 8 + 2 * c4;
                float v0 = acc[i][j][half * 2], v1 = acc[i][j][half * 2 + 1];
                if (bias) {
                    const float2 bv = *reinterpret_cast<const float2*>(bias + col);
                    v0 += bv.x; v1 += bv.y;
                }
                v0 *= alpha; v1 *= alpha;
                if (reluFlag) { v0 = fmaxf(v0, 0.f); v1 = fmaxf(v1, 0.f); }
                if (outMode == 0) {
                    *reinterpret_cast<uint2*>(OA + (size_t)row * ldc + col) =
                        make_uint2(packA(v0), packA(v1));
                } else {
                    size_t off;
                    if (outMode == 1) off = (size_t)row * ldc + col;
                    else off = (size_t)(z * 1024 + (row >> 6)) * 8192 + (row & 63) * 128 + col;
                    uint32_t w10, w20, w11, w21;
                    packB2(v0, w10, w20);
                    packB2(v1, w11, w21);
                    *reinterpret_cast<uint2*>(O0 + off) = make_uint2(w10, w11);
                    *reinterpret_cast<uint2*>(O1 + off) = make_uint2(w20, w21);
                }
            }
        }
    }
#undef AS
#undef B1
#undef B2
}

__global__ void split_U_kernel(const float* __restrict__ U)
{
    const int idx = blockIdx.x * 256 + threadIdx.x;
    eU[idx] = packA(U[idx]);
}
__global__ void transpose_U_kernel(const float* __restrict__ U)
{
    __shared__ float t[32][33];
    const int z = blockIdx.z, i0 = blockIdx.y * 32, j0 = blockIdx.x * 32;
    const int tx = threadIdx.x, ty = threadIdx.y;
    for (int yy = 0; yy < 4; yy++)
        t[ty + 8 * yy][tx] = U[(size_t)z * 1048576 + (size_t)(i0 + ty + 8 * yy) * 1024 + j0 + tx];
    __syncthreads();
    for (int yy = 0; yy < 4; yy++)
        eUt[(size_t)z * 1048576 + (size_t)(j0 + ty + 8 * yy) * 1024 + i0 + tx] =
            packA(t[tx][ty + 8 * yy]);
}
__global__ void split_x_kernel(const float* __restrict__ x)
{
    const int idx = blockIdx.x * 256 + threadIdx.x;
    const int d = idx & 63, b = (idx >> 6) & 63, j = idx >> 12;
    uint32_t w1, w2;
    packB2(x[(size_t)b * 65536 + (size_t)j * 64 + d], w1, w2);
    const size_t off = (size_t)j * 4096 + b * 64 + d;
    eHa[off] = w1;
    eHa[8388608u + off] = w2;
}
__global__ void split_w_kernel(const float* __restrict__ w1, int n1,
                               const float* __restrict__ w2, int n2)
{
    const int idx = blockIdx.x * 256 + threadIdx.x;
    uint32_t a, b;
    if (idx < n1) { packB2(w1[idx], a, b); eW1[idx] = a; eW1[49152u + idx] = b; }
    if (idx < n2) { packB2(w2[idx], a, b); eW2[idx] = a; eW2[49152u + idx] = b; }
}

__global__ void pool_kernel()
{
    const int b = blockIdx.x, t = threadIdx.x;
    const int d = t & 127, s = t >> 7;
    float sum = 0.f;
    for (int i = s; i < 1024; i += 4) {
        const size_t off = (size_t)i * 8192 + b * 128 + d;
        sum += __half2float(__ushort_as_half((unsigned short)(eHb[off] & 0xFFFF)))
             + __half2float(__ushort_as_half((unsigned short)(eHb[8388608u + off] & 0xFFFF)));
    }
    __shared__ float red[512];
    red[t] = sum;
    __syncthreads();
    if (s == 0)
        g_pooled[b * 128 + d] =
            (red[d] + red[d + 128] + red[d + 256] + red[d + 384]) * (1.f / 1024.f);
}

__global__ void classifier_kernel(const float* __restrict__ Wc1,
                                  const float* __restrict__ bc1,
                                  const float* __restrict__ al,
                                  const float* __restrict__ Wc2,
                                  const float* __restrict__ bc2,
                                  float* __restrict__ out)
{
    __shared__ float zs[64][128];
    const int t = threadIdx.x;
    for (int idx = t; idx < 64 * 128; idx += 256) {
        const int b = idx >> 7, h = idx & 127;
        float acc = bc1[h];
        for (int d = 0; d < 128; d++)
            acc = fmaf(g_pooled[b * 128 + d], Wc1[d * 128 + h], acc);
        zs[b][h] = acc > 0.f ? acc : al[h] * acc;
    }
    __syncthreads();
    const int b = t >> 2, c = t & 3;
    float acc = bc2[c];
    for (int h = 0; h < 128; h++)
        acc = fmaf(zs[b][h], Wc2[h * 4 + c], acc);
    out[b * 4 + c] = acc;
}

// ---------------------------------------------------------------------------
extern "C" void kernel_launch(void* const* d_in, const int* in_sizes, int n_in,
                              void* d_out, int out_size)
{
    const float* x    = (const float*)d_in[0];
    const float* U    = (const float*)d_in[1];
    const float* w1_0 = (const float*)d_in[2];
    const float* b1_0 = (const float*)d_in[3];
    const float* w2_0 = (const float*)d_in[4];
    const float* b2_0 = (const float*)d_in[5];
    const float* w1_r = (const float*)d_in[6];
    const float* b1_r = (const float*)d_in[7];
    const float* w2_r = (const float*)d_in[8];
    const float* b2_r = (const float*)d_in[9];
    const float* bw   = (const float*)d_in[10];
    const float* Wc1  = (const float*)d_in[11];
    const float* bc1  = (const float*)d_in[12];
    const float* alp  = (const float*)d_in[13];
    const float* Wc2  = (const float*)d_in[14];
    const float* bc2  = (const float*)d_in[15];
    float* out = (float*)d_out;

    cudaFuncSetAttribute(gemm_h, cudaFuncAttributeMaxDynamicSharedMemorySize, SMEM_BYTES);

    split_U_kernel<<<12288, 256>>>(U);
    transpose_U_kernel<<<dim3(32, 32, 3), dim3(32, 8)>>>(U);
    split_x_kernel<<<16384, 256>>>(x);

    int hinTag = 0, houtTag = 1;
    for (int l = 0; l < 3; l++) {
        const int Din   = (l == 0) ? 64 : 128;
        const int Wcols = 64 * Din;
        const float* w1 = (l == 0) ? w1_0 : (w1_r + (size_t)(l - 1) * 3 * 128 * 128);
        const float* b1 = (l == 0) ? b1_0 : (b1_r + (size_t)(l - 1) * 3 * 128);
        const float* w2 = (l == 0) ? w2_0 : (w2_r + (size_t)(l - 1) * 3 * 128 * 128);
        const float* b2 = (l == 0) ? b2_0 : (b2_r + (size_t)(l - 1) * 3 * 128);

        split_w_kernel<<<192, 256>>>(w1, 3 * Din * 128, w2, 3 * 128 * 128);

        // 1) AGG_z = U_z^T @ H -> eAGG (A-role)
        gemm_h<<<dim3(Wcols / 128, 8, 3), 256, SMEM_BYTES>>>(
            0, 1048576LL, 1024, 1,
            hinTag, 0LL, 8388608LL, Wcols,
            2, 8388608LL, 0LL, Wcols, 0,
            1024, nullptr, 0, nullptr, 0, 0);
        // 2) M1_z = relu(AGG_z @ w1_z + b1_z) -> eM1 (A-role)
        gemm_h<<<dim3(1, 512, 3), 256, SMEM_BYTES>>>(
            2, 8388608LL, Din, 0,
            2, (long long)Din * 128, 49152LL, 128,
            3, 8388608LL, 0LL, 128, 0,
            Din, b1, 128, nullptr, 0, 1);
        // 3) M2_z = ws_z * (M1_z @ w2_z + b2_z) -> eM2 scatter (B-role)
        gemm_h<<<dim3(1, 512, 3), 256, SMEM_BYTES>>>(
            3, 8388608LL, 128, 0,
            3, 16384LL, 49152LL, 128,
            4, 0LL, 25165824LL, 0, 2,
            128, b2, 128, bw, l, 0);
        // 4) H_out = relu(Ucat @ M2_all), single K=3072 GEMM
        gemm_h<<<dim3(64, 8, 1), 256, SMEM_BYTES>>>(
            1, 0LL, 1024, 1,
            4, 0LL, 25165824LL, 8192,
            houtTag, 0LL, 8388608LL, 8192, 1,
            3072, nullptr, 0, nullptr, 0, 1);

        const int t = hinTag; hinTag = houtTag; houtTag = t;
    }

    pool_kernel<<<64, 512>>>();
    classifier_kernel<<<1, 256>>>(Wc1, bc1, alp, Wc2, bc2, out);
}

// round 11
// speedup vs baseline: 2.2605x; 1.1585x over previous
#include <cuda_runtime.h>
#include <cuda_fp16.h>
#include <cstdint>

// 3-term fp16-split GEMM. Word packs logical ks (k, k+8) of its k16 block.
// D = Ah*Bh + Al*Bh + Ah*Bl. A: m-major 2-plane. B: k-word-row 2-plane.

#define A_RS 12
#define B_RS 136
#define STG_W (2 * 128 * A_RS + 2 * 8 * B_RS)   // 5248 words
#define NSTG 3
#define SMEM_BYTES (NSTG * STG_W * 4)            // 62976

// A-role: [plane0|plane1], rows m, K/2 words/row
__device__ uint32_t eUt  [2u * 1572864u];   // [z][i][512]  zs=524288
__device__ uint32_t eUcat[2u * 1572864u];   // [i][1536]
__device__ uint32_t eAGG [2u * 12582912u];  // zs=4194304 (b-major flat [b*1024+i][Din/2])
__device__ uint32_t eM1  [2u * 12582912u];  // [m'][64]
// B-role: word rows kp=(k>>4)*8+(k&7), cols n
__device__ uint32_t eM2  [2u * 12582912u];  // [1536][8192]
__device__ uint32_t eHx  [2u * 2097152u];   // [512][4096]
__device__ uint32_t eHa  [2u * 4194304u];   // [512][8192]
__device__ uint32_t eHb  [2u * 4194304u];
__device__ uint32_t eW1  [2u * 24576u];     // [z][64][128] zs=8192
__device__ uint32_t eW2  [2u * 24576u];
__device__ float    g_pooled[64 * 128];

__device__ __forceinline__ uint32_t* resolve(int t) {
    switch (t) {
        case 0: return eUt;  case 1: return eUcat; case 2: return eAGG;
        case 3: return eM1;  case 4: return eM2;   case 5: return eHx;
        case 6: return eHa;  case 7: return eHb;   case 8: return eW1;
        default: return eW2;
    }
}

__device__ __forceinline__ void hsplit(float v, uint32_t& h, uint32_t& l) {
    __half hh = __float2half_rn(v);
    __half ll = __float2half_rn(v - __half2float(hh));
    h = (uint32_t)__half_as_ushort(hh);
    l = (uint32_t)__half_as_ushort(ll);
}
__device__ __forceinline__ uint32_t pck(uint32_t a, uint32_t b) { return a | (b << 16); }

__device__ __forceinline__ uint32_t sm2u(const void* p) {
    return (uint32_t)__cvta_generic_to_shared(p);
}
#define CP16(dst, src) \
    asm volatile("cp.async.cg.shared.global [%0], [%1], 16;" :: "r"(dst), "l"(src))
#define CP_COMMIT() asm volatile("cp.async.commit_group;")
#define CP_WAIT1()  asm volatile("cp.async.wait_group 1;")

#define MMA16(d, a, b0, b1)                                                   \
    asm volatile(                                                             \
        "mma.sync.aligned.m16n8k16.row.col.f32.f16.f16.f32 "                  \
        "{%0,%1,%2,%3},{%4,%5,%6,%7},{%8,%9},{%0,%1,%2,%3};"                  \
        : "+f"(d[0]), "+f"(d[1]), "+f"(d[2]), "+f"(d[3])                      \
        : "r"(a[0]), "r"(a[1]), "r"(a[2]), "r"(a[3]), "r"(b0), "r"(b1))

// ---------------------------------------------------------------------------
__global__ void __launch_bounds__(256, 2)
gemm3(int aTag, long long aZ, long long aP, int ldaW,
      int bTag, long long bZ, long long bP, int ldbW,
      int oTag, long long oZ, long long oP, int ldoW, int outMode, int Din,
      int K, const float* __restrict__ bias, int biasZ,
      const float* __restrict__ bwPtr, int bwL, int reluFlag)
{
    extern __shared__ uint32_t smw[];
    const int z = blockIdx.z, bx = blockIdx.x, by = blockIdx.y;
    const uint32_t* A = resolve(aTag) + (long long)z * aZ;
    const uint32_t* B = resolve(bTag) + (long long)z * bZ;
    if (bias) bias += z * biasZ;

    const int tid = threadIdx.x, warp = tid >> 5, lane = tid & 31;
    const int warpM = (warp >> 2) * 64, warpN = (warp & 3) * 32;
    const int c4 = lane & 3, g = lane >> 2;

    float acc[4][4][4];
#pragma unroll
    for (int i = 0; i < 4; i++)
#pragma unroll
        for (int j = 0; j < 4; j++)
#pragma unroll
            for (int r = 0; r < 4; r++) acc[i][j][r] = 0.f;

    const int ar = tid >> 1, ahw = (tid & 1) * 4;       // A loader
    const int br = tid >> 5, bc = (tid & 31) * 4;       // B loader

    auto issue_stage = [&](int s, int st) {
        const int base = st * STG_W;
        const uint32_t* srcA = A + (size_t)(by * 128 + ar) * ldaW + s * 8 + ahw;
        CP16(sm2u(smw + base + ar * A_RS + ahw), srcA);
        CP16(sm2u(smw + base + 1536 + ar * A_RS + ahw), srcA + aP);
        const uint32_t* srcB = B + (size_t)(s * 8 + br) * ldbW + bx * 128 + bc;
        CP16(sm2u(smw + base + 3072 + br * B_RS + bc), srcB);
        CP16(sm2u(smw + base + 4160 + br * B_RS + bc), srcB + bP);
        CP_COMMIT();
    };

    const int NS = K >> 4;
    issue_stage(0, 0);
    issue_stage(1, 1);

    for (int s = 0; s < NS; s++) {
        const int cur = s % 3;
        CP_WAIT1();
        __syncthreads();
        if (s + 2 < NS) issue_stage(s + 2, (s + 2) % 3);
        else            CP_COMMIT();

        const int base = cur * STG_W;
        uint32_t bh[4][2], bl[4][2];
#pragma unroll
        for (int j = 0; j < 4; j++) {
            const int n = warpN + j * 8 + g;
            bh[j][0] = smw[base + 3072 + c4 * B_RS + n];
            bh[j][1] = smw[base + 3072 + (c4 + 4) * B_RS + n];
            bl[j][0] = smw[base + 4160 + c4 * B_RS + n];
            bl[j][1] = smw[base + 4160 + (c4 + 4) * B_RS + n];
        }
#pragma unroll
        for (int it = 0; it < 4; it++) {
            const int m = warpM + it * 16 + g;
            const int ab = base + m * A_RS;
            uint32_t ah[4], al[4];
            ah[0] = smw[ab + c4];                 ah[1] = smw[ab + 8 * A_RS + c4];
            ah[2] = smw[ab + c4 + 4];             ah[3] = smw[ab + 8 * A_RS + c4 + 4];
            al[0] = smw[ab + 1536 + c4];          al[1] = smw[ab + 1536 + 8 * A_RS + c4];
            al[2] = smw[ab + 1536 + c4 + 4];      al[3] = smw[ab + 1536 + 8 * A_RS + c4 + 4];
#pragma unroll
            for (int j = 0; j < 4; j++) {
                MMA16(acc[it][j], ah, bh[j][0], bh[j][1]);
                MMA16(acc[it][j], al, bh[j][0], bh[j][1]);
                MMA16(acc[it][j], ah, bl[j][0], bl[j][1]);
            }
        }
        __syncthreads();
    }

    float alpha = 1.f;
    if (bwPtr) {
        const float w0 = bwPtr[bwL * 3], w1 = bwPtr[bwL * 3 + 1], w2 = bwPtr[bwL * 3 + 2];
        const float mx = fmaxf(w0, fmaxf(w1, w2));
        const float e0 = expf(w0 - mx), e1 = expf(w1 - mx), e2 = expf(w2 - mx);
        alpha = (z == 0 ? e0 : (z == 1 ? e1 : e2)) / (e0 + e1 + e2);
    }

    uint32_t* OH = resolve(oTag) + (long long)z * oZ;
    uint32_t* OL = OH + oP;

    auto post = [&](float v, int n) -> float {
        if (bias) v += bias[n];
        v *= alpha;
        if (reluFlag) v = fmaxf(v, 0.f);
        return v;
    };

    if (outMode == 0 || outMode == 3) {
        // A-role output: word packs cols (n, n+8) -> j-tile pairs
#pragma unroll
        for (int it = 0; it < 4; it++) {
#pragma unroll
            for (int half = 0; half < 2; half++) {
                const int row = by * 128 + warpM + it * 16 + g + 8 * half;
#pragma unroll
                for (int jp = 0; jp < 2; jp++) {
                    uint32_t wh[2], wl[2];
                    int n0 = 0;
#pragma unroll
                    for (int s = 0; s < 2; s++) {
                        const int n = bx * 128 + warpN + 16 * jp + 2 * c4 + s;
                        if (s == 0) n0 = n;
                        const float v0 = post(acc[it][2 * jp][half * 2 + s], n);
                        const float v1 = post(acc[it][2 * jp + 1][half * 2 + s], n + 8);
                        uint32_t h0, l0, h1, l1;
                        hsplit(v0, h0, l0);
                        hsplit(v1, h1, l1);
                        wh[s] = pck(h0, h1);
                        wl[s] = pck(l0, l1);
                    }
                    size_t ad;
                    if (outMode == 0) {
                        ad = (size_t)row * ldoW + (n0 >> 4) * 8 + (n0 & 7);
                    } else {
                        const int bb = n0 / Din, dr = n0 % Din;
                        ad = (size_t)bb * (1024 * (Din / 2)) + (size_t)row * (Din / 2)
                           + (dr >> 4) * 8 + (dr & 7);
                    }
                    *reinterpret_cast<uint2*>(OH + ad) = make_uint2(wh[0], wh[1]);
                    *reinterpret_cast<uint2*>(OL + ad) = make_uint2(wl[0], wl[1]);
                }
            }
        }
    } else {
        // B-role output: word packs rows (k, k+8) -> half pairs
#pragma unroll
        for (int it = 0; it < 4; it++) {
            const int r0 = by * 128 + warpM + it * 16 + g;
            const int kk = (outMode == 1) ? r0 : z * 1024 + (r0 & 1023);
            const int wr = (kk >> 4) * 8 + (kk & 7);
            const int bb = r0 >> 10;
#pragma unroll
            for (int j = 0; j < 4; j++) {
                uint32_t wh[2], wl[2];
                int nc0 = 0;
#pragma unroll
                for (int s = 0; s < 2; s++) {
                    const int n = warpN + j * 8 + 2 * c4 + s;
                    const int nc = (outMode == 1) ? bx * 128 + n : bb * 128 + n;
                    if (s == 0) nc0 = nc;
                    const float v0 = post(acc[it][j][s], n);
                    const float v1 = post(acc[it][j][2 + s], n);
                    uint32_t h0, l0, h1, l1;
                    hsplit(v0, h0, l0);
                    hsplit(v1, h1, l1);
                    wh[s] = pck(h0, h1);
                    wl[s] = pck(l0, l1);
                }
                const size_t ad = (size_t)wr * ldoW + nc0;
                *reinterpret_cast<uint2*>(OH + ad) = make_uint2(wh[0], wh[1]);
                *reinterpret_cast<uint2*>(OL + ad) = make_uint2(wl[0], wl[1]);
            }
        }
    }
}

// ---------------- prep kernels ----------------
__global__ void prep_Ut(const float* __restrict__ U)
{
    const int idx = blockIdx.x * 256 + threadIdx.x;   // 1572864
    const int z = idx >> 19, rem = idx & 524287, i = rem >> 9, w = rem & 511;
    const int jlo = ((w >> 3) << 4) + (w & 7);
    const float v0 = U[((size_t)z << 20) + ((size_t)jlo << 10) + i];
    const float v1 = U[((size_t)z << 20) + ((size_t)(jlo + 8) << 10) + i];
    uint32_t h0, l0, h1, l1;
    hsplit(v0, h0, l0); hsplit(v1, h1, l1);
    eUt[idx] = pck(h0, h1);
    eUt[1572864u + idx] = pck(l0, l1);
}
__global__ void prep_Ucat(const float* __restrict__ U)
{
    const int idx = blockIdx.x * 256 + threadIdx.x;   // 1572864
    const int i = idx / 1536, w = idx % 1536;
    const int klo = ((w >> 3) << 4) + (w & 7);
    const int z = klo >> 10, j = klo & 1023;
    const float v0 = U[((size_t)z << 20) + ((size_t)i << 10) + j];
    const float v1 = U[((size_t)z << 20) + ((size_t)i << 10) + j + 8];
    uint32_t h0, l0, h1, l1;
    hsplit(v0, h0, l0); hsplit(v1, h1, l1);
    eUcat[idx] = pck(h0, h1);
    eUcat[1572864u + idx] = pck(l0, l1);
}
__global__ void prep_x(const float* __restrict__ x)
{
    const int idx = blockIdx.x * 256 + threadIdx.x;   // 2097152
    const int kp = idx >> 12, n = idx & 4095;
    const int jlo = ((kp >> 3) << 4) + (kp & 7);
    const int b = n >> 6, d = n & 63;
    const float v0 = x[((size_t)b << 16) + ((size_t)jlo << 6) + d];
    const float v1 = x[((size_t)b << 16) + ((size_t)(jlo + 8) << 6) + d];
    uint32_t h0, l0, h1, l1;
    hsplit(v0, h0, l0); hsplit(v1, h1, l1);
    eHx[idx] = pck(h0, h1);
    eHx[2097152u + idx] = pck(l0, l1);
}
__global__ void prep_w(const float* __restrict__ w1, int Din,
                       const float* __restrict__ w2)
{
    const int idx = blockIdx.x * 256 + threadIdx.x;   // 24576
    const int rows1 = Din / 2;
    if (idx < 3 * rows1 * 128) {
        const int z = idx / (rows1 * 128), wr = (idx / 128) % rows1, h = idx % 128;
        const int dlo = ((wr >> 3) << 4) + (wr & 7);
        const float v0 = w1[(size_t)z * Din * 128 + (size_t)dlo * 128 + h];
        const float v1 = w1[(size_t)z * Din * 128 + (size_t)(dlo + 8) * 128 + h];
        uint32_t h0, l0, h1, l1;
        hsplit(v0, h0, l0); hsplit(v1, h1, l1);
        eW1[z * 8192 + wr * 128 + h] = pck(h0, h1);
        eW1[24576u + z * 8192 + wr * 128 + h] = pck(l0, l1);
    }
    {
        const int z = idx / 8192, wr = (idx / 128) % 64, h = idx % 128;
        const int dlo = ((wr >> 3) << 4) + (wr & 7);
        const float v0 = w2[(size_t)z * 16384 + (size_t)dlo * 128 + h];
        const float v1 = w2[(size_t)z * 16384 + (size_t)(dlo + 8) * 128 + h];
        uint32_t h0, l0, h1, l1;
        hsplit(v0, h0, l0); hsplit(v1, h1, l1);
        eW2[idx] = pck(h0, h1);
        eW2[24576u + idx] = pck(l0, l1);
    }
}

__global__ void pool_kernel()
{
    const int b = blockIdx.x, t = threadIdx.x;
    const int d = t & 127, s4 = t >> 7;
    float sum = 0.f;
    for (int wr = s4; wr < 512; wr += 4) {
        const size_t off = (size_t)wr * 8192 + b * 128 + d;
        const uint32_t wh = eHa[off], wl = eHa[4194304u + off];
        sum += __half2float(__ushort_as_half((unsigned short)(wh & 0xFFFF)))
             + __half2float(__ushort_as_half((unsigned short)(wh >> 16)))
             + __half2float(__ushort_as_half((unsigned short)(wl & 0xFFFF)))
             + __half2float(__ushort_as_half((unsigned short)(wl >> 16)));
    }
    __shared__ float red[512];
    red[t] = sum;
    __syncthreads();
    if (s4 == 0)
        g_pooled[b * 128 + d] =
            (red[d] + red[d + 128] + red[d + 256] + red[d + 384]) * (1.f / 1024.f);
}

__global__ void classifier_kernel(const float* __restrict__ Wc1,
                                  const float* __restrict__ bc1,
                                  const float* __restrict__ al,
                                  const float* __restrict__ Wc2,
                                  const float* __restrict__ bc2,
                                  float* __restrict__ out)
{
    __shared__ float zs[64][128];
    const int t = threadIdx.x;
    for (int idx = t; idx < 64 * 128; idx += 256) {
        const int b = idx >> 7, h = idx & 127;
        float acc = bc1[h];
        for (int d = 0; d < 128; d++)
            acc = fmaf(g_pooled[b * 128 + d], Wc1[d * 128 + h], acc);
        zs[b][h] = acc > 0.f ? acc : al[h] * acc;
    }
    __syncthreads();
    const int b = t >> 2, c = t & 3;
    float acc = bc2[c];
    for (int h = 0; h < 128; h++)
        acc = fmaf(zs[b][h], Wc2[h * 4 + c], acc);
    out[b * 4 + c] = acc;
}

// ---------------------------------------------------------------------------
extern "C" void kernel_launch(void* const* d_in, const int* in_sizes, int n_in,
                              void* d_out, int out_size)
{
    const float* x    = (const float*)d_in[0];
    const float* U    = (const float*)d_in[1];
    const float* w1_0 = (const float*)d_in[2];
    const float* b1_0 = (const float*)d_in[3];
    const float* w2_0 = (const float*)d_in[4];
    const float* b2_0 = (const float*)d_in[5];
    const float* w1_r = (const float*)d_in[6];
    const float* b1_r = (const float*)d_in[7];
    const float* w2_r = (const float*)d_in[8];
    const float* b2_r = (const float*)d_in[9];
    const float* bw   = (const float*)d_in[10];
    const float* Wc1  = (const float*)d_in[11];
    const float* bc1  = (const float*)d_in[12];
    const float* alp  = (const float*)d_in[13];
    const float* Wc2  = (const float*)d_in[14];
    const float* bc2  = (const float*)d_in[15];
    float* out = (float*)d_out;

    cudaFuncSetAttribute(gemm3, cudaFuncAttributeMaxDynamicSharedMemorySize, SMEM_BYTES);

    prep_Ut<<<6144, 256>>>(U);
    prep_Ucat<<<6144, 256>>>(U);
    prep_x<<<8192, 256>>>(x);

    int hinTag = 5, houtTag = 6;   // l0 in: eHx; outs: eHa, eHb, eHa
    for (int l = 0; l < 3; l++) {
        const int Din   = (l == 0) ? 64 : 128;
        const int Wcols = 64 * Din;
        const float* w1 = (l == 0) ? w1_0 : (w1_r + (size_t)(l - 1) * 3 * 128 * 128);
        const float* b1 = (l == 0) ? b1_0 : (b1_r + (size_t)(l - 1) * 3 * 128);
        const float* w2 = (l == 0) ? w2_0 : (w2_r + (size_t)(l - 1) * 3 * 128 * 128);
        const float* b2 = (l == 0) ? b2_0 : (b2_r + (size_t)(l - 1) * 3 * 128);
        const long long hP  = (l == 0) ? 2097152LL : 4194304LL;
        const int       hLd = (l == 0) ? 4096 : 8192;

        prep_w<<<96, 256>>>(w1, Din, w2);

        // G1: AGG_z = U_z^T @ H  (mode3 -> eAGG b-major flat)
        gemm3<<<dim3(Wcols / 128, 8, 3), 256, SMEM_BYTES>>>(
            0, 524288LL, 1572864LL, 512,
            hinTag, 0LL, hP, hLd,
            2, 4194304LL, 12582912LL, 0, 3, Din,
            1024, nullptr, 0, nullptr, 0, 0);
        // G2: M1_z = relu(AGG_z @ w1_z + b1_z)  (mode0 -> eM1)
        gemm3<<<dim3(1, 512, 3), 256, SMEM_BYTES>>>(
            2, 4194304LL, 12582912LL, Din / 2,
            8, 8192LL, 24576LL, 128,
            3, 4194304LL, 12582912LL, 64, 0, 0,
            Din, b1, 128, nullptr, 0, 1);
        // G3: M2_z = ws_z*(M1_z @ w2_z + b2_z)  (mode2 -> eM2)
        gemm3<<<dim3(1, 512, 3), 256, SMEM_BYTES>>>(
            3, 4194304LL, 12582912LL, 64,
            9, 8192LL, 24576LL, 128,
            4, 0LL, 12582912LL, 8192, 2, 0,
            128, b2, 128, bw, l, 0);
        // G4: H_out = relu(Ucat @ M2_all)  (mode1 -> eH)
        gemm3<<<dim3(64, 8, 1), 256, SMEM_BYTES>>>(
            1, 0LL, 1572864LL, 1536,
            4, 0LL, 12582912LL, 8192,
            houtTag, 0LL, 4194304LL, 8192, 1, 0,
            3072, nullptr, 0, nullptr, 0, 1);

        hinTag = houtTag;
        houtTag = (houtTag == 6) ? 7 : 6;
    }

    pool_kernel<<<64, 512>>>();
    classifier_kernel<<<1, 256>>>(Wc1, bc1, alp, Wc2, bc2, out);
}